// round 6
// baseline (speedup 1.0000x reference)
#include <cuda_runtime.h>
#include <cstdint>

#define BQ     32
#define NKEYS  4096
#define DIM    64
#define NQ     8
#define CPB    16         // chunks per batch -> grid 512
#define CHUNK  256        // keys per CTA (8 warps x 32)
#define WKEYS  32
#define TKEYS  4          // keys per warp-tile
#define NT     8          // tiles per warp
#define NBUF   3
#define KP     68         // padded K/Q row stride (floats)

typedef unsigned long long u64;

// ---- global scratch ----
__device__ float    g_pv[BQ * CPB * NQ * DIM];
__device__ float    g_cs[BQ * CPB * NQ];
__device__ unsigned g_cnt[BQ];

// ---- cp.async ----
__device__ __forceinline__ void cp16(uint32_t s, const float* g) {
    asm volatile("cp.async.cg.shared.global [%0], [%1], 16;\n" :: "r"(s), "l"(g));
}
__device__ __forceinline__ void cp_commit() {
    asm volatile("cp.async.commit_group;\n" ::: "memory");
}
template <int N>
__device__ __forceinline__ void cp_wait() {
    asm volatile("cp.async.wait_group %0;\n" :: "n"(N) : "memory");
}

// ---- packed f32x2 FMA ----
__device__ __forceinline__ void fma2(u64& d, u64 a, u64 b) {
    asm("fma.rn.f32x2 %0, %1, %2, %0;" : "+l"(d) : "l"(a), "l"(b));
}
__device__ __forceinline__ float f2lo(u64 x) { return __uint_as_float((unsigned)x); }
__device__ __forceinline__ float f2hi(u64 x) { return __uint_as_float((unsigned)(x >> 32)); }

// ---- smem layout (floats) ----
// Q: 8 x KP = 544
// per-warp: K NBUF x (4 x KP = 272) | V NBUF x (4 x 64 = 256) | P (4 x 16)
#define W_KSZ   (TKEYS * KP)                   // 272
#define W_VSZ   (TKEYS * DIM)                  // 256
#define W_K     0
#define W_V     (NBUF * W_KSZ)                 // 816
#define W_P     (W_V + NBUF * W_VSZ)           // 1584
#define W_SZ    (W_P + TKEYS * 16)             // 1648
#define OFF_Q   0
#define OFF_W(w) (544 + (w) * W_SZ)
#define SMEM_FLOATS (544 + 8 * W_SZ)           // 13728 floats = 54,912 B -> 4 CTAs/SM

extern __shared__ float smem[];

__global__ __launch_bounds__(256, 4)
void attn_fused(const float* __restrict__ keys,
                const float* __restrict__ vals,
                const float* __restrict__ query,
                float* __restrict__ out) {
    const int tid  = threadIdx.x;
    const int lane = tid & 31;
    const int warp = tid >> 5;
    const int b     = blockIdx.x >> 4;
    const int chunk = blockIdx.x & 15;
    const int n0    = chunk * CHUNK;
    __shared__ int s_last;

    const uint32_t sbase = (uint32_t)__cvta_generic_to_shared(smem);
    const uint32_t wK = sbase + (uint32_t)((OFF_W(warp) + W_K) << 2);
    const uint32_t wV = sbase + (uint32_t)((OFF_W(warp) + W_V) << 2);

    const float* kg = keys + ((size_t)b * NKEYS + n0 + warp * WKEYS) * DIM;
    const float* vg = vals + ((size_t)b * NKEYS + n0 + warp * WKEYS) * DIM;

    // ---- stage tile t (4 keys): 2 K + 2 V cp.async per lane, one group ----
    auto stage = [&](int t) {
        const int buf = t % NBUF;
        const float* kt = kg + t * TKEYS * DIM;
        const float* vt = vg + t * TKEYS * DIM;
        const uint32_t kd = wK + (uint32_t)((buf * W_KSZ) << 2);
        const uint32_t vd = wV + (uint32_t)((buf * W_VSZ) << 2);
#pragma unroll
        for (int i = 0; i < 2; ++i) {               // K: 64 x 16B chunks
            int c = i * 32 + lane;
            int r = c >> 4, s = (c & 15) << 2;
            cp16(kd + (uint32_t)((r * KP + s) << 2), kt + r * DIM + s);
        }
#pragma unroll
        for (int i = 0; i < 2; ++i) {               // V: 64 x 16B chunks, linear
            int c = i * 32 + lane;
            cp16(vd + (uint32_t)(c << 4), vt + c * 4);
        }
        cp_commit();
    };

    stage(0); stage(1); stage(2);

    // ---- Q into smem ----
    if (tid < 128) {
        int r = tid >> 4, s = (tid & 15) << 2;
        *(float4*)&smem[OFF_Q + r * KP + s] =
            *(const float4*)(query + ((size_t)b * NQ + r) * DIM + s);
    }
    __syncthreads();

    const int key = lane >> 3;            // 0..3 : key within tile
    const int m   = lane & 7;             // 0..7 : query
    const float* Kme = &smem[OFF_W(warp) + W_K + key * KP];
    const float* Qme = &smem[OFF_Q + m * KP];
    const float* Vw  = &smem[OFF_W(warp) + W_V];
    float*       Pw  = &smem[OFF_W(warp) + W_P];

    float cs = 0.f;
    u64 pv[8];
#pragma unroll
    for (int i = 0; i < 8; ++i) pv[i] = 0ull;

#pragma unroll
    for (int t = 0; t < NT; ++t) {
        const int buf = t % NBUF;
        if (t < NT - 2)       cp_wait<2>();
        else if (t == NT - 2) cp_wait<1>();
        else                  cp_wait<0>();
        __syncwarp();

        // ---- QK: lane = (key, m), full 64-d dot ----
        {
            const float* kr = Kme + buf * W_KSZ;
            u64 acc = 0ull;
#pragma unroll
            for (int d4 = 0; d4 < 16; ++d4) {
                ulonglong2 kv = *(const ulonglong2*)(kr  + (d4 << 2));
                ulonglong2 qv = *(const ulonglong2*)(Qme + (d4 << 2));
                fma2(acc, kv.x, qv.x);
                fma2(acc, kv.y, qv.y);
            }
            float a = (f2lo(acc) + f2hi(acc)) * 0.125f;

            // softmax over the 8 m-lanes of this key
            float mx = a;
            mx = fmaxf(mx, __shfl_xor_sync(0xffffffffu, mx, 1));
            mx = fmaxf(mx, __shfl_xor_sync(0xffffffffu, mx, 2));
            mx = fmaxf(mx, __shfl_xor_sync(0xffffffffu, mx, 4));
            float e = __expf(a - mx);
            float sum = e;
            sum += __shfl_xor_sync(0xffffffffu, sum, 1);
            sum += __shfl_xor_sync(0xffffffffu, sum, 2);
            sum += __shfl_xor_sync(0xffffffffu, sum, 4);
            float p = e * (1.0f / sum) + 1e-8f;
            cs += p;
            // splatted store: (p,p) at P[key][2m]
            *(float2*)&Pw[key * 16 + (m << 1)] = make_float2(p, p);
        }
        __syncwarp();

        // ---- PV: 4 keys, lane owns v-pair (2*lane) ----
        {
            const float* vb = Vw + buf * W_VSZ + (lane << 1);
#pragma unroll
            for (int k = 0; k < TKEYS; ++k) {
                u64 vv = *(const u64*)(vb + k * DIM);
                const ulonglong2* pr = (const ulonglong2*)&Pw[k * 16];
                ulonglong2 p01 = pr[0], p23 = pr[1], p45 = pr[2], p67 = pr[3];
                fma2(pv[0], p01.x, vv); fma2(pv[1], p01.y, vv);
                fma2(pv[2], p23.x, vv); fma2(pv[3], p23.y, vv);
                fma2(pv[4], p45.x, vv); fma2(pv[5], p45.y, vv);
                fma2(pv[6], p67.x, vv); fma2(pv[7], p67.y, vv);
            }
        }
        __syncwarp();

        if (t + 3 < NT) stage(t + 3);
    }

    // ---- per-warp partials into own region ----
    {
        float* red = &smem[OFF_W(warp)];
#pragma unroll
        for (int q = 0; q < 8; ++q)
            *(float2*)&red[q * 64 + (lane << 1)] = make_float2(f2lo(pv[q]), f2hi(pv[q]));
        // cs currently per (key,m) lane; reduce over the 4 key groups (stride 8)
        cs += __shfl_xor_sync(0xffffffffu, cs, 8);
        cs += __shfl_xor_sync(0xffffffffu, cs, 16);
        if (lane < 8) red[512 + m] = cs;
    }
    __syncthreads();

    const int pidx = (b * CPB + chunk) * NQ;
    if (tid < 8) {
        float s = 0.f;
#pragma unroll
        for (int w = 0; w < 8; ++w) s += smem[OFF_W(w) + 512 + tid];
        g_cs[pidx + tid] = s;
    }
    {
        int q = tid >> 5, v2 = (tid & 31) << 1;
        float s0 = 0.f, s1 = 0.f;
#pragma unroll
        for (int w = 0; w < 8; ++w) {
            float2 p = *(const float2*)&smem[OFF_W(w) + q * 64 + v2];
            s0 += p.x; s1 += p.y;
        }
        *(float2*)&g_pv[((size_t)pidx + q) * DIM + v2] = make_float2(s0, s1);
    }

    // ---- fused finalize ----
    __syncthreads();
    if (tid == 0) {
        __threadfence();
        unsigned old = atomicAdd(&g_cnt[b], 1u);
        s_last = (old == CPB - 1) ? 1 : 0;
    }
    __syncthreads();
    if (s_last) {
        __threadfence();
        int q = tid >> 5, v2 = (tid & 31) << 1;
        float c0 = 0.f, a0 = 0.f, a1 = 0.f;
#pragma unroll
        for (int c = 0; c < CPB; ++c) {
            c0 += g_cs[(b * CPB + c) * NQ + q];
            float2 p = *(const float2*)&g_pv[((size_t)(b * CPB + c) * NQ + q) * DIM + v2];
            a0 += p.x; a1 += p.y;
        }
        float inv = 1.0f / c0;
        *(float2*)&out[((size_t)b * NQ + q) * DIM + v2] = make_float2(a0 * inv, a1 * inv);
        if (tid == 0) g_cnt[b] = 0;   // reset for next graph replay
    }
}

extern "C" void kernel_launch(void* const* d_in, const int* in_sizes, int n_in,
                              void* d_out, int out_size) {
    const float* keys  = (const float*)d_in[0];
    const float* vals  = (const float*)d_in[1];
    const float* query = (const float*)d_in[2];
    float* out = (float*)d_out;

    cudaFuncSetAttribute(attn_fused,
                         cudaFuncAttributeMaxDynamicSharedMemorySize,
                         SMEM_FLOATS * sizeof(float));
    attn_fused<<<BQ * CPB, 256, SMEM_FLOATS * sizeof(float)>>>(keys, vals, query, out);
}